// round 3
// baseline (speedup 1.0000x reference)
#include <cuda_runtime.h>
#include <cstdint>

#define BB 8
#define NN 4096
#define DD 16
#define OO 64
#define KK 20
#define KP 24   // fast-pass pad: top-24 kept, re-ranked with emulated-ref d2
#define CNT (8LL*4096*20)

// ---------------- scratch (static device globals: no allocation) ------------
__device__ float  g_u[BB*NN*OO];     // (W1-W2)·x   per point, [p][o]
__device__ float  g_v[BB*NN*OO];     // W2·x        per point, [p][o]
__device__ int    g_idx[BB*NN*KK];   // knn indices (within batch), [p][k]
__device__ float  g_sqf[BB*NN];      // XLA-emulated fp32 of sum(x*x)
__device__ double g_sum[OO];
__device__ double g_sumsq[OO];
__device__ float  g_a[OO];
__device__ float  g_c[OO];

// ---------------- kernel 0: zero the per-channel accumulators ----------------
__global__ void zero_sums() {
    int t = threadIdx.x;
    if (t < OO) { g_sum[t] = 0.0; g_sumsq[t] = 0.0; }
}

// ---------------- kernel 0b: XLA-emulated per-point squared norms -----------
// Emulates XLA GPU row-reduction of jnp.sum(x*x, axis=-1) for row=16:
// vectorized-by-4 multi-row warp reduce: each lane serially accumulates 4
// rounded squares (mul then add, no fma), then shuffle tree over 4 lanes:
// result = (s0 + s2) + (s1 + s3).
__global__ void sq_kernel(const float* __restrict__ x) {
    int p = blockIdx.x * blockDim.x + threadIdx.x;
    const float4* xp = (const float4*)(x + (size_t)p * DD);
    float s[4];
#pragma unroll
    for (int i = 0; i < 4; i++) {
        float4 v = xp[i];
        float a = __fmul_rn(v.x, v.x);
        a = __fadd_rn(a, __fmul_rn(v.y, v.y));
        a = __fadd_rn(a, __fmul_rn(v.z, v.z));
        a = __fadd_rn(a, __fmul_rn(v.w, v.w));
        s[i] = a;
    }
    g_sqf[p] = __fadd_rn(__fadd_rn(s[0], s[2]), __fadd_rn(s[1], s[3]));
}

// ---------------- kernel 1: per-point projections u, v ----------------------
// h[b,o,n,k] = W1·x_n + W2·(x_g - x_n) = u[n,o] + v[g,o]
__global__ void proj_kernel(const float* __restrict__ x,
                            const float* __restrict__ W) {
    __shared__ float Wt[2*DD][OO];
    __shared__ float xr[4][DD];
    int tid = threadIdx.x;
    for (int i = tid; i < OO*2*DD; i += blockDim.x) {
        int o = i / (2*DD), c = i % (2*DD);
        Wt[c][o] = W[i];
    }
    int p0 = blockIdx.x * 4;
    if (tid < 4*DD) {
        xr[tid >> 4][tid & 15] = x[p0*DD + tid];
    }
    __syncthreads();
    int o  = tid & 63;
    int nl = tid >> 6;
    float cacc = 0.f, facc = 0.f;
#pragma unroll
    for (int d = 0; d < DD; d++) {
        float xv = xr[nl][d];
        cacc = fmaf(Wt[d][o],      xv, cacc);
        facc = fmaf(Wt[DD + d][o], xv, facc);
    }
    int p = p0 + nl;
    g_u[p*OO + o] = cacc - facc;
    g_v[p*OO + o] = facc;
}

// ---------------- kernel 2: brute-force kNN --------------------------------
#define TQ 64
#define TC 512

__device__ __forceinline__ float dot4(float4 a, float4 b) {
    return fmaf(a.x, b.x, fmaf(a.y, b.y, fmaf(a.z, b.z, a.w * b.w)));
}

__device__ __forceinline__ unsigned long long pack_key(float d, int gidx) {
    unsigned s = __float_as_uint(d);
    s ^= ((unsigned)((int)s >> 31)) | 0x80000000u;   // monotone f32->u32
    return ((unsigned long long)s << 32) | (unsigned)gidx;
}

// sorted-array insert: single u64 compare == lexicographic (d2 asc, idx asc)
// == jax top_k(-d2) tie-breaking.
template<int L>
__device__ __forceinline__ void tk_insert(unsigned long long* heap,
                                          unsigned long long key) {
    if (key < heap[L-1]) {
        heap[L-1] = key;
#pragma unroll
        for (int j = L-1; j > 0; --j) {
            if (heap[j] < heap[j-1]) {
                unsigned long long t = heap[j];
                heap[j] = heap[j-1];
                heap[j-1] = t;
            } else break;
        }
    }
}

__global__ __launch_bounds__(TQ, 8) void knn_kernel(const float* __restrict__ x) {
    __shared__ float4 xs[TC*4];   // candidate tile, row-major [m][d/4]
    __shared__ float  sqs[TC];
    int tid = threadIdx.x;
    int b   = blockIdx.x >> 6;
    int qn  = ((blockIdx.x & 63) << 6) + tid;
    const float* xb  = x + (size_t)b * NN * DD;
    const float* sqb = g_sqf + (size_t)b * NN;

    const float4* qp = (const float4*)(xb + (size_t)qn * DD);
    float4 q0 = qp[0], q1 = qp[1], q2 = qp[2], q3 = qp[3];
    float sqn = sqb[qn];

    unsigned long long heap[KP];
#pragma unroll
    for (int j = 0; j < KP; j++) heap[j] = 0xFFFFFFFFFFFFFFFFull;

    for (int t0 = 0; t0 < NN; t0 += TC) {
#pragma unroll
        for (int i = 0; i < TC/TQ; i++) {
            int r = tid + i * TQ;
            const float4* src = (const float4*)(xb + (size_t)(t0 + r) * DD);
            xs[r*4 + 0] = src[0]; xs[r*4 + 1] = src[1];
            xs[r*4 + 2] = src[2]; xs[r*4 + 3] = src[3];
            sqs[r] = sqb[t0 + r];
        }
        __syncthreads();

        for (int m = 0; m < TC; m += 2) {
            float4 c0 = xs[m*4+0], c1 = xs[m*4+1], c2 = xs[m*4+2], c3 = xs[m*4+3];
            float4 e0 = xs[m*4+4], e1 = xs[m*4+5], e2 = xs[m*4+6], e3 = xs[m*4+7];
            float dA = (dot4(q0,c0) + dot4(q1,c1)) + (dot4(q2,c2) + dot4(q3,c3));
            float dB = (dot4(q0,e0) + dot4(q1,e1)) + (dot4(q2,e2) + dot4(q3,e3));
            float d2A = fmaf(-2.f, dA, sqn + sqs[m]);
            float d2B = fmaf(-2.f, dB, sqn + sqs[m+1]);
            tk_insert<KP>(heap, pack_key(d2A, t0 + m));
            tk_insert<KP>(heap, pack_key(d2B, t0 + m + 1));
        }
        __syncthreads();
    }

    // ---- refinement: emulate the REFERENCE's rounding for the finalists ----
    // dot: cuBLAS fp32 sgemm semantics — single accumulator, serial FFMA over
    //      k = 0..15 ascending.
    // d2 : fl( fl(sq_n + sq_m) - fl(2*dot) )   (Python left-to-right)
    // sq : XLA-emulated (g_sqf above).
    unsigned long long outk[KK];
#pragma unroll
    for (int j = 0; j < KK; j++) outk[j] = 0xFFFFFFFFFFFFFFFFull;

#pragma unroll
    for (int j = 0; j < KP; j++) {
        int ci = (int)(heap[j] & 0xFFFFFFFFu);
        const float4* cp = (const float4*)(xb + (size_t)ci * DD);
        float4 c0 = cp[0], c1 = cp[1], c2 = cp[2], c3 = cp[3];
        float acc = 0.f;
        acc = fmaf(q0.x, c0.x, acc); acc = fmaf(q0.y, c0.y, acc);
        acc = fmaf(q0.z, c0.z, acc); acc = fmaf(q0.w, c0.w, acc);
        acc = fmaf(q1.x, c1.x, acc); acc = fmaf(q1.y, c1.y, acc);
        acc = fmaf(q1.z, c1.z, acc); acc = fmaf(q1.w, c1.w, acc);
        acc = fmaf(q2.x, c2.x, acc); acc = fmaf(q2.y, c2.y, acc);
        acc = fmaf(q2.z, c2.z, acc); acc = fmaf(q2.w, c2.w, acc);
        acc = fmaf(q3.x, c3.x, acc); acc = fmaf(q3.y, c3.y, acc);
        acc = fmaf(q3.w == q3.w ? q3.z : q3.z, c3.z, acc);  // keep strict order
        acc = fmaf(q3.w, c3.w, acc);
        float ssum = __fadd_rn(sqn, sqb[ci]);
        float d2   = __fsub_rn(ssum, __fmul_rn(2.0f, acc));
        tk_insert<KK>(outk, pack_key(d2, ci));
    }

    int* outp = g_idx + ((size_t)b * NN + qn) * KK;
#pragma unroll
    for (int j = 0; j < KK; j++) outp[j] = (int)(outk[j] & 0xFFFFFFFFu);
}

// ---------------- kernel 3: per-channel sum / sumsq over (b,n,k) ------------
__global__ void sums_kernel() {
    int tid = threadIdx.x;
    int o = tid & 63;
    int g = tid >> 6;
    float s = 0.f, s2 = 0.f;
    int r0 = (blockIdx.x * 4 + g) * 32;
    for (int i = 0; i < 32; i++) {
        int r = r0 + i;
        int b = r >> 12;
        float u = g_u[(size_t)r * OO + o];
        const int* ip = g_idx + (size_t)r * KK;
#pragma unroll
        for (int k = 0; k < KK; k++) {
            int gi = ip[k];
            float h = u + g_v[(((size_t)b << 12) + gi) * OO + o];
            s += h;
            s2 = fmaf(h, h, s2);
        }
    }
    atomicAdd(&g_sum[o],   (double)s);
    atomicAdd(&g_sumsq[o], (double)s2);
}

// ---------------- kernel 4: finalize affine coefficients --------------------
__global__ void finalize_kernel(const float* __restrict__ gamma,
                                const float* __restrict__ beta) {
    int o = threadIdx.x;
    if (o < OO) {
        double mean = g_sum[o] / (double)CNT;
        double var  = g_sumsq[o] / (double)CNT - mean * mean;
        double rstd = 1.0 / sqrt(var + 1e-5);
        float a = gamma[o] * (float)rstd;
        g_a[o] = a;
        g_c[o] = fmaf(-(float)mean, a, beta[o]);
    }
}

// ---------------- kernel 5: write output (coalesced, smem-staged) -----------
__global__ void out_kernel(float* __restrict__ out) {
    __shared__ float su[NN];
    __shared__ float sv[NN];
    int b = blockIdx.x >> 6;
    int o = blockIdx.x & 63;
    float a = g_a[o], c = g_c[o];
    int tid = threadIdx.x;
    size_t base = (size_t)b * NN * OO;
    for (int i = tid; i < NN; i += blockDim.x) {
        su[i] = fmaf(a, g_u[base + (size_t)i * OO + o], c);
        sv[i] = a * g_v[base + (size_t)i * OO + o];
    }
    __syncthreads();
    const int* ip = g_idx + (size_t)b * NN * KK;
    float* op = out + (size_t)blockIdx.x * (NN * KK);
    for (int e = tid; e < NN * KK; e += blockDim.x) {
        int n = e / KK;
        int gi = ip[e];
        float y = su[n] + sv[gi];
        op[e] = fmaxf(y, 0.f);
    }
}

// ---------------- launcher ---------------------------------------------------
extern "C" void kernel_launch(void* const* d_in, const int* in_sizes, int n_in,
                              void* d_out, int out_size) {
    const float* x     = (const float*)d_in[0];
    const float* W     = (const float*)d_in[1];
    const float* gamma = (const float*)d_in[2];
    const float* beta  = (const float*)d_in[3];
    float* out = (float*)d_out;

    zero_sums<<<1, 64>>>();
    sq_kernel<<<BB*NN/256, 256>>>(x);
    proj_kernel<<<BB*NN/4, 256>>>(x, W);
    knn_kernel<<<BB*NN/TQ, TQ>>>(x);
    sums_kernel<<<BB*NN/128, 256>>>();
    finalize_kernel<<<1, 64>>>(gamma, beta);
    out_kernel<<<BB*OO, 256>>>(out);
}

// round 4
// speedup vs baseline: 1.9941x; 1.9941x over previous
#include <cuda_runtime.h>
#include <math_constants.h>
#include <cstdint>

#define BB 8
#define NN 4096
#define DD 16
#define OO 64
#define KK 20
#define KP 24          // per-half fast-pass pad
#define SPLIT 2        // candidate split per query
#define HALF (NN/SPLIT)
#define CNT (8LL*4096*20)

#define TQ 64          // queries per block (1 thread = 1 query)
#define TC 256         // candidate tile rows
#define BUFCAP 512     // per-thread pending-candidate buffer (local mem)

// ---------------- scratch (static device globals: no allocation) ------------
__device__ float  g_u[BB*NN*OO];
__device__ float  g_v[BB*NN*OO];
__device__ int    g_idx[BB*NN*KK];          // final knn indices
__device__ int    g_pidx[BB*NN*SPLIT*KP];   // per-half fast top-24 indices
__device__ float  g_sqf[BB*NN];             // XLA-emulated fp32 sum(x*x)
__device__ double g_sum[OO];
__device__ double g_sumsq[OO];
__device__ float  g_a[OO];
__device__ float  g_c[OO];

// ---------------- kernel 0: zero accumulators --------------------------------
__global__ void zero_sums() {
    int t = threadIdx.x;
    if (t < OO) { g_sum[t] = 0.0; g_sumsq[t] = 0.0; }
}

// ---------------- kernel 0b: XLA-emulated per-point squared norms -----------
// vec4 serial mul/add per lane, then (s0+s2)+(s1+s3). DO NOT CHANGE (bit-exact
// emulation of the reference's rounding; validated round 3).
__global__ void sq_kernel(const float* __restrict__ x) {
    int p = blockIdx.x * blockDim.x + threadIdx.x;
    const float4* xp = (const float4*)(x + (size_t)p * DD);
    float s[4];
#pragma unroll
    for (int i = 0; i < 4; i++) {
        float4 v = xp[i];
        float a = __fmul_rn(v.x, v.x);
        a = __fadd_rn(a, __fmul_rn(v.y, v.y));
        a = __fadd_rn(a, __fmul_rn(v.z, v.z));
        a = __fadd_rn(a, __fmul_rn(v.w, v.w));
        s[i] = a;
    }
    g_sqf[p] = __fadd_rn(__fadd_rn(s[0], s[2]), __fadd_rn(s[1], s[3]));
}

// ---------------- kernel 1: per-point projections u, v ----------------------
__global__ void proj_kernel(const float* __restrict__ x,
                            const float* __restrict__ W) {
    __shared__ float Wt[2*DD][OO];
    __shared__ float xr[4][DD];
    int tid = threadIdx.x;
    for (int i = tid; i < OO*2*DD; i += blockDim.x) {
        int o = i / (2*DD), c = i % (2*DD);
        Wt[c][o] = W[i];
    }
    int p0 = blockIdx.x * 4;
    if (tid < 4*DD) xr[tid >> 4][tid & 15] = x[p0*DD + tid];
    __syncthreads();
    int o  = tid & 63;
    int nl = tid >> 6;
    float cacc = 0.f, facc = 0.f;
#pragma unroll
    for (int d = 0; d < DD; d++) {
        float xv = xr[nl][d];
        cacc = fmaf(Wt[d][o],      xv, cacc);
        facc = fmaf(Wt[DD + d][o], xv, facc);
    }
    int p = p0 + nl;
    g_u[p*OO + o] = cacc - facc;
    g_v[p*OO + o] = facc;
}

// ---------------- kNN helpers ------------------------------------------------
__device__ __forceinline__ float dot4(float4 a, float4 b) {
    return fmaf(a.x, b.x, fmaf(a.y, b.y, fmaf(a.z, b.z, a.w * b.w)));
}

__device__ __forceinline__ unsigned long long pack_key(float d, int gidx) {
    unsigned s = __float_as_uint(d);
    s ^= ((unsigned)((int)s >> 31)) | 0x80000000u;   // monotone f32->u32
    return ((unsigned long long)s << 32) | (unsigned)gidx;
}

__device__ __forceinline__ float unpack_d2(unsigned long long key) {
    unsigned s = (unsigned)(key >> 32);
    s = (s & 0x80000000u) ? (s ^ 0x80000000u) : ~s;
    return __uint_as_float(s);
}

// drain pending buffer into this thread's smem-resident sorted top-24 column.
// hcol[j*TQ] = j-th best key. Rare path (runs a few times per thread total).
__device__ __forceinline__ void compact(unsigned long long* __restrict__ buf,
                                        int& cnt,
                                        unsigned long long* __restrict__ hcol,
                                        float& thr) {
    unsigned long long worst = hcol[(KP-1)*TQ];
    for (int i = 0; i < cnt; i++) {
        unsigned long long key = buf[i];
        if (key < worst) {
            int j = KP - 1;
            while (j > 0) {
                unsigned long long cur = hcol[(j-1)*TQ];
                if (key < cur) { hcol[j*TQ] = cur; j--; }
                else break;
            }
            hcol[j*TQ] = key;
            worst = hcol[(KP-1)*TQ];
        }
    }
    cnt = 0;
    thr = unpack_d2(worst);
}

// ---------------- kernel 2a: fast-pass kNN, candidate-split ------------------
// grid = BB * (NN/TQ) * SPLIT blocks; 1 thread = 1 query over HALF candidates.
// Hot loop: pure FMA + one float compare + predicated buffer push.
__global__ __launch_bounds__(TQ) void knn_part_kernel(const float* __restrict__ x) {
    __shared__ float4 xs[TC*4];
    __shared__ float  sqs[TC];
    __shared__ unsigned long long heap[KP*TQ];   // [j][thread]

    int tid  = threadIdx.x;
    int bi   = blockIdx.x;
    int b    = bi >> 7;            // 128 blocks per batch
    int rem  = bi & 127;
    int qg   = rem >> 1;
    int half = rem & 1;
    int qn   = qg * TQ + tid;
    int cbase = half * HALF;

    const float* xb  = x + (size_t)b * NN * DD;
    const float* sqb = g_sqf + (size_t)b * NN;

    const float4* qp = (const float4*)(xb + (size_t)qn * DD);
    float4 q0 = qp[0], q1 = qp[1], q2 = qp[2], q3 = qp[3];
    float sqn = sqb[qn];

#pragma unroll
    for (int j = 0; j < KP; j++) heap[j*TQ + tid] = 0xFFFFFFFFFFFFFFFFull;
    unsigned long long* hcol = heap + tid;

    unsigned long long buf[BUFCAP];   // local memory (dynamically indexed)
    int cnt = 0;
    float thr = CUDART_INF_F;

    for (int t0 = 0; t0 < HALF; t0 += TC) {
        // stage tile
#pragma unroll
        for (int i = 0; i < TC/TQ; i++) {
            int r = tid + i * TQ;
            const float4* src = (const float4*)(xb + (size_t)(cbase + t0 + r) * DD);
            xs[r*4 + 0] = src[0]; xs[r*4 + 1] = src[1];
            xs[r*4 + 2] = src[2]; xs[r*4 + 3] = src[3];
            sqs[r] = sqb[cbase + t0 + r];
        }
        __syncthreads();

#pragma unroll 4
        for (int m = 0; m < TC; m++) {
            float4 c0 = xs[m*4+0], c1 = xs[m*4+1], c2 = xs[m*4+2], c3 = xs[m*4+3];
            float d  = (dot4(q0,c0) + dot4(q1,c1)) + (dot4(q2,c2) + dot4(q3,c3));
            float d2 = fmaf(-2.f, d, sqn + sqs[m]);
            if (d2 < thr) {
                buf[cnt++] = pack_key(d2, cbase + t0 + m);
            }
        }
        __syncthreads();

        // establish threshold after first tile; afterwards only drain when the
        // buffer could overflow within the next tile (warp-uniform trigger).
        bool need = (t0 == 0) || __any_sync(0xffffffffu, cnt >= BUFCAP - TC);
        if (need) compact(buf, cnt, hcol, thr);
    }
    compact(buf, cnt, hcol, thr);

    int* outp = g_pidx + (((size_t)b * NN + qn) * SPLIT + half) * KP;
#pragma unroll
    for (int j = 0; j < KP; j++) outp[j] = (int)(hcol[j*TQ] & 0xFFFFFFFFu);
}

// ---------------- kernel 2b: merge halves + emulated-reference refinement ---
// Re-ranks the 2*KP finalists with the reference's exact rounding (validated
// round 3: serial-FFMA dot k ascending; d2 = fl(fl(sqn+sqc) - fl(2*dot))).
__global__ __launch_bounds__(TQ) void knn_merge_kernel(const float* __restrict__ x) {
    int tid = threadIdx.x;
    int b   = blockIdx.x >> 6;
    int qn  = ((blockIdx.x & 63) << 6) + tid;
    const float* xb  = x + (size_t)b * NN * DD;
    const float* sqb = g_sqf + (size_t)b * NN;

    const float4* qp = (const float4*)(xb + (size_t)qn * DD);
    float4 q0 = qp[0], q1 = qp[1], q2 = qp[2], q3 = qp[3];
    float sqn = sqb[qn];

    unsigned long long outk[KK];
#pragma unroll
    for (int j = 0; j < KK; j++) outk[j] = 0xFFFFFFFFFFFFFFFFull;

    const int* pin = g_pidx + ((size_t)b * NN + qn) * SPLIT * KP;
#pragma unroll 2
    for (int j = 0; j < SPLIT * KP; j++) {
        int ci = pin[j];
        const float4* cp = (const float4*)(xb + (size_t)ci * DD);
        float4 c0 = cp[0], c1 = cp[1], c2 = cp[2], c3 = cp[3];
        float acc = 0.f;
        acc = fmaf(q0.x, c0.x, acc); acc = fmaf(q0.y, c0.y, acc);
        acc = fmaf(q0.z, c0.z, acc); acc = fmaf(q0.w, c0.w, acc);
        acc = fmaf(q1.x, c1.x, acc); acc = fmaf(q1.y, c1.y, acc);
        acc = fmaf(q1.z, c1.z, acc); acc = fmaf(q1.w, c1.w, acc);
        acc = fmaf(q2.x, c2.x, acc); acc = fmaf(q2.y, c2.y, acc);
        acc = fmaf(q2.z, c2.z, acc); acc = fmaf(q2.w, c2.w, acc);
        acc = fmaf(q3.x, c3.x, acc); acc = fmaf(q3.y, c3.y, acc);
        acc = fmaf(q3.z, c3.z, acc); acc = fmaf(q3.w, c3.w, acc);
        float ssum = __fadd_rn(sqn, sqb[ci]);
        float d2   = __fsub_rn(ssum, __fmul_rn(2.0f, acc));
        unsigned long long key = pack_key(d2, ci);
        if (key < outk[KK-1]) {
            outk[KK-1] = key;
#pragma unroll
            for (int t = KK-1; t > 0; --t) {
                if (outk[t] < outk[t-1]) {
                    unsigned long long tmp = outk[t];
                    outk[t] = outk[t-1]; outk[t-1] = tmp;
                } else break;
            }
        }
    }

    int* outp = g_idx + ((size_t)b * NN + qn) * KK;
#pragma unroll
    for (int j = 0; j < KK; j++) outp[j] = (int)(outk[j] & 0xFFFFFFFFu);
}

// ---------------- kernel 3: per-channel sum / sumsq over (b,n,k) ------------
__global__ void sums_kernel() {
    int tid = threadIdx.x;
    int o = tid & 63;
    int g = tid >> 6;
    float s = 0.f, s2 = 0.f;
    int r0 = (blockIdx.x * 4 + g) * 32;
    for (int i = 0; i < 32; i++) {
        int r = r0 + i;
        int b = r >> 12;
        float u = g_u[(size_t)r * OO + o];
        const int* ip = g_idx + (size_t)r * KK;
#pragma unroll
        for (int k = 0; k < KK; k++) {
            int gi = ip[k];
            float h = u + g_v[(((size_t)b << 12) + gi) * OO + o];
            s += h;
            s2 = fmaf(h, h, s2);
        }
    }
    atomicAdd(&g_sum[o],   (double)s);
    atomicAdd(&g_sumsq[o], (double)s2);
}

// ---------------- kernel 4: finalize affine coefficients --------------------
__global__ void finalize_kernel(const float* __restrict__ gamma,
                                const float* __restrict__ beta) {
    int o = threadIdx.x;
    if (o < OO) {
        double mean = g_sum[o] / (double)CNT;
        double var  = g_sumsq[o] / (double)CNT - mean * mean;
        double rstd = 1.0 / sqrt(var + 1e-5);
        float a = gamma[o] * (float)rstd;
        g_a[o] = a;
        g_c[o] = fmaf(-(float)mean, a, beta[o]);
    }
}

// ---------------- kernel 5: write output (coalesced, smem-staged) -----------
__global__ void out_kernel(float* __restrict__ out) {
    __shared__ float su[NN];
    __shared__ float sv[NN];
    int b = blockIdx.x >> 6;
    int o = blockIdx.x & 63;
    float a = g_a[o], c = g_c[o];
    int tid = threadIdx.x;
    size_t base = (size_t)b * NN * OO;
    for (int i = tid; i < NN; i += blockDim.x) {
        su[i] = fmaf(a, g_u[base + (size_t)i * OO + o], c);
        sv[i] = a * g_v[base + (size_t)i * OO + o];
    }
    __syncthreads();
    const int* ip = g_idx + (size_t)b * NN * KK;
    float* op = out + (size_t)blockIdx.x * (NN * KK);
    for (int e = tid; e < NN * KK; e += blockDim.x) {
        int n = e / KK;
        int gi = ip[e];
        float y = su[n] + sv[gi];
        op[e] = fmaxf(y, 0.f);
    }
}

// ---------------- launcher ---------------------------------------------------
extern "C" void kernel_launch(void* const* d_in, const int* in_sizes, int n_in,
                              void* d_out, int out_size) {
    const float* x     = (const float*)d_in[0];
    const float* W     = (const float*)d_in[1];
    const float* gamma = (const float*)d_in[2];
    const float* beta  = (const float*)d_in[3];
    float* out = (float*)d_out;

    zero_sums<<<1, 64>>>();
    sq_kernel<<<BB*NN/256, 256>>>(x);
    proj_kernel<<<BB*NN/4, 256>>>(x, W);
    knn_part_kernel<<<BB*(NN/TQ)*SPLIT, TQ>>>(x);
    knn_merge_kernel<<<BB*NN/TQ, TQ>>>(x);
    sums_kernel<<<BB*NN/128, 256>>>();
    finalize_kernel<<<1, 64>>>(gamma, beta);
    out_kernel<<<BB*OO, 256>>>(out);
}